// round 1
// baseline (speedup 1.0000x reference)
#include <cuda_runtime.h>
#include <math.h>

// Problem constants
#define N_ROWS 32768
#define D_IN   3000
#define H0     1024
#define H1     256
#define K_CL   20

// SGEMM tiling
#define BM 128
#define BN 128
#define BK 8
#define TM 8
#define TN 8
// threads per block = (BM/TM)*(BN/TN) = 16*16 = 256

// Scratch for hidden activations H [N_ROWS, H0] (fp32, 134 MB)
__device__ float g_H[(size_t)N_ROWS * H0];

// ---------------------------------------------------------------------------
// Tiled SGEMM: C[M,N] = act(A[M,K] @ B[K,N] + bias[N])
// A row-major (lda = K), B row-major (ldb = N), C row-major (ldc = N).
// Requires: M % BM == 0, N % BN == 0, K % BK == 0, K % 4 == 0, N % 4 == 0.
// SILU: apply x*sigmoid(x) in epilogue.
// ---------------------------------------------------------------------------
template <bool SILU>
__global__ __launch_bounds__(256, 2)
void sgemm_bias_act(const float* __restrict__ A,
                    const float* __restrict__ B,
                    const float* __restrict__ bias,
                    float* __restrict__ C,
                    int M, int N, int K)
{
    __shared__ float As[BK][BM];   // transposed A tile
    __shared__ float Bs[BK][BN];

    const int tid = threadIdx.x;
    const int blockRow = blockIdx.y;   // M tile
    const int blockCol = blockIdx.x;   // N tile

    const int threadRow = tid / (BN / TN);   // 0..15
    const int threadCol = tid % (BN / TN);   // 0..15

    // A tile load mapping: 128 rows x 8 cols = 256 float4
    const int aRow  = tid >> 1;          // 0..127
    const int aCol4 = (tid & 1) * 4;     // 0 or 4
    // B tile load mapping: 8 rows x 128 cols = 256 float4
    const int bRow  = tid >> 5;          // 0..7
    const int bCol4 = (tid & 31) * 4;    // 0..124

    const float* Aptr = A + (size_t)(blockRow * BM) * K;
    const float* Bptr = B + (size_t)(blockCol * BN);

    float acc[TM][TN];
    #pragma unroll
    for (int i = 0; i < TM; i++)
        #pragma unroll
        for (int j = 0; j < TN; j++)
            acc[i][j] = 0.0f;

    float regA[TM];
    float regB[TN];

    for (int k0 = 0; k0 < K; k0 += BK) {
        // Load A tile (transposed into As)
        {
            const float4 v = *reinterpret_cast<const float4*>(
                Aptr + (size_t)aRow * K + k0 + aCol4);
            As[aCol4 + 0][aRow] = v.x;
            As[aCol4 + 1][aRow] = v.y;
            As[aCol4 + 2][aRow] = v.z;
            As[aCol4 + 3][aRow] = v.w;
        }
        // Load B tile
        {
            const float4 v = *reinterpret_cast<const float4*>(
                Bptr + (size_t)(k0 + bRow) * N + bCol4);
            *reinterpret_cast<float4*>(&Bs[bRow][bCol4]) = v;
        }
        __syncthreads();

        #pragma unroll
        for (int k = 0; k < BK; k++) {
            #pragma unroll
            for (int i = 0; i < TM; i++) regA[i] = As[k][threadRow * TM + i];
            #pragma unroll
            for (int j = 0; j < TN; j++) regB[j] = Bs[k][threadCol * TN + j];
            #pragma unroll
            for (int i = 0; i < TM; i++)
                #pragma unroll
                for (int j = 0; j < TN; j++)
                    acc[i][j] = fmaf(regA[i], regB[j], acc[i][j]);
        }
        __syncthreads();
    }

    // Epilogue: bias + optional SiLU, vectorized stores
    const int cRowBase = blockRow * BM + threadRow * TM;
    const int cColBase = blockCol * BN + threadCol * TN;

    float bv[TN];
    #pragma unroll
    for (int j = 0; j < TN; j++) bv[j] = bias[cColBase + j];

    #pragma unroll
    for (int i = 0; i < TM; i++) {
        float vals[TN];
        #pragma unroll
        for (int j = 0; j < TN; j++) {
            float v = acc[i][j] + bv[j];
            if (SILU) {
                v = v / (1.0f + expf(-v));
            }
            vals[j] = v;
        }
        float* out = C + (size_t)(cRowBase + i) * N + cColBase;
        #pragma unroll
        for (int j = 0; j < TN; j += 4) {
            float4 v4 = make_float4(vals[j], vals[j+1], vals[j+2], vals[j+3]);
            *reinterpret_cast<float4*>(out + j) = v4;
        }
    }
}

// ---------------------------------------------------------------------------
// Soft assignment: q[n,c] = (1/(1+d2)) / sum_c (1/(1+d2)); V=1 so exponent = 1.
// One warp per row; lane c (< 20) owns cluster c. Clusters staged in smem.
// ---------------------------------------------------------------------------
__global__ __launch_bounds__(256)
void soft_assign_kernel(const float* __restrict__ Z,       // [N_ROWS, H1]
                        const float* __restrict__ clusters,// [K_CL, H1]
                        float* __restrict__ Q)             // [N_ROWS, K_CL]
{
    __shared__ float sCl[K_CL][H1];   // 20 KB

    const int tid = threadIdx.x;
    for (int i = tid; i < K_CL * H1; i += blockDim.x)
        sCl[i / H1][i % H1] = clusters[i];
    __syncthreads();

    const int warpId = tid >> 5;
    const int lane   = tid & 31;
    const int row    = blockIdx.x * 8 + warpId;
    if (row >= N_ROWS) return;

    const float* z = Z + (size_t)row * H1;

    float d2 = 0.0f;
    if (lane < K_CL) {
        #pragma unroll 8
        for (int d = 0; d < H1; d++) {
            float diff = z[d] - sCl[lane][d];   // z[d] is a warp-uniform load
            d2 = fmaf(diff, diff, d2);
        }
    }
    float q = (lane < K_CL) ? 1.0f / (1.0f + d2) : 0.0f;

    // warp-wide sum
    float s = q;
    #pragma unroll
    for (int off = 16; off > 0; off >>= 1)
        s += __shfl_xor_sync(0xFFFFFFFFu, s, off);

    if (lane < K_CL)
        Q[(size_t)row * K_CL + lane] = q / s;
}

// ---------------------------------------------------------------------------
extern "C" void kernel_launch(void* const* d_in, const int* in_sizes, int n_in,
                              void* d_out, int out_size)
{
    const float* x        = (const float*)d_in[0];   // [N_ROWS, D_IN]
    const float* W1       = (const float*)d_in[1];   // [D_IN, H0]
    const float* b1       = (const float*)d_in[2];   // [H0]
    const float* W2       = (const float*)d_in[3];   // [H0, H1]
    const float* b2       = (const float*)d_in[4];   // [H1]
    const float* clusters = (const float*)d_in[5];   // [K_CL, H1]

    float* z_out = (float*)d_out;                          // [N_ROWS, H1]
    float* q_out = (float*)d_out + (size_t)N_ROWS * H1;    // [N_ROWS, K_CL]

    float* H;
    cudaGetSymbolAddress((void**)&H, g_H);

    // GEMM1: H = silu(x @ W1 + b1)   [32768,3000]x[3000,1024]
    {
        dim3 grid(H0 / BN, N_ROWS / BM);
        sgemm_bias_act<true><<<grid, 256>>>(x, W1, b1, H, N_ROWS, H0, D_IN);
    }
    // GEMM2: Z = H @ W2 + b2   [32768,1024]x[1024,256]
    {
        dim3 grid(H1 / BN, N_ROWS / BM);
        sgemm_bias_act<false><<<grid, 256>>>(H, W2, b2, z_out, N_ROWS, H1, H0);
    }
    // Soft assignment
    {
        dim3 grid(N_ROWS / 8);
        soft_assign_kernel<<<grid, 256>>>(z_out, clusters, q_out);
    }
}

// round 2
// speedup vs baseline: 1.0006x; 1.0006x over previous
#include <cuda_runtime.h>
#include <math.h>

// Problem constants
#define N_ROWS 32768
#define D_IN   3000
#define H0     1024
#define H1     256
#define K_CL   20

// SGEMM tiling
#define BM 128
#define BN 128
#define BK 8
#define TM 8
#define TN 8
// threads per block = (BM/TM)*(BN/TN) = 16*16 = 256

// Scratch for hidden activations H [N_ROWS, H0] (fp32, 134 MB)
__device__ float g_H[(size_t)N_ROWS * H0];

// ---------------------------------------------------------------------------
// Tiled SGEMM: C[M,N] = act(A[M,K] @ B[K,N] + bias[N])
// A row-major (lda = K), B row-major (ldb = N), C row-major (ldc = N).
// Requires: M % BM == 0, N % BN == 0, K % BK == 0, K % 4 == 0, N % 4 == 0.
// SILU: apply x*sigmoid(x) in epilogue.
// ---------------------------------------------------------------------------
template <bool SILU>
__global__ __launch_bounds__(256, 2)
void sgemm_bias_act(const float* __restrict__ A,
                    const float* __restrict__ B,
                    const float* __restrict__ bias,
                    float* __restrict__ C,
                    int M, int N, int K)
{
    __shared__ float As[BK][BM];   // transposed A tile
    __shared__ float Bs[BK][BN];

    const int tid = threadIdx.x;
    const int blockRow = blockIdx.y;   // M tile
    const int blockCol = blockIdx.x;   // N tile

    const int threadRow = tid / (BN / TN);   // 0..15
    const int threadCol = tid % (BN / TN);   // 0..15

    // A tile load mapping: 128 rows x 8 cols = 256 float4
    const int aRow  = tid >> 1;          // 0..127
    const int aCol4 = (tid & 1) * 4;     // 0 or 4
    // B tile load mapping: 8 rows x 128 cols = 256 float4
    const int bRow  = tid >> 5;          // 0..7
    const int bCol4 = (tid & 31) * 4;    // 0..124

    const float* Aptr = A + (size_t)(blockRow * BM) * K;
    const float* Bptr = B + (size_t)(blockCol * BN);

    float acc[TM][TN];
    #pragma unroll
    for (int i = 0; i < TM; i++)
        #pragma unroll
        for (int j = 0; j < TN; j++)
            acc[i][j] = 0.0f;

    float regA[TM];
    float regB[TN];

    for (int k0 = 0; k0 < K; k0 += BK) {
        // Load A tile (transposed into As)
        {
            const float4 v = *reinterpret_cast<const float4*>(
                Aptr + (size_t)aRow * K + k0 + aCol4);
            As[aCol4 + 0][aRow] = v.x;
            As[aCol4 + 1][aRow] = v.y;
            As[aCol4 + 2][aRow] = v.z;
            As[aCol4 + 3][aRow] = v.w;
        }
        // Load B tile
        {
            const float4 v = *reinterpret_cast<const float4*>(
                Bptr + (size_t)(k0 + bRow) * N + bCol4);
            *reinterpret_cast<float4*>(&Bs[bRow][bCol4]) = v;
        }
        __syncthreads();

        #pragma unroll
        for (int k = 0; k < BK; k++) {
            #pragma unroll
            for (int i = 0; i < TM; i++) regA[i] = As[k][threadRow * TM + i];
            #pragma unroll
            for (int j = 0; j < TN; j++) regB[j] = Bs[k][threadCol * TN + j];
            #pragma unroll
            for (int i = 0; i < TM; i++)
                #pragma unroll
                for (int j = 0; j < TN; j++)
                    acc[i][j] = fmaf(regA[i], regB[j], acc[i][j]);
        }
        __syncthreads();
    }

    // Epilogue: bias + optional SiLU, vectorized stores
    const int cRowBase = blockRow * BM + threadRow * TM;
    const int cColBase = blockCol * BN + threadCol * TN;

    float bv[TN];
    #pragma unroll
    for (int j = 0; j < TN; j++) bv[j] = bias[cColBase + j];

    #pragma unroll
    for (int i = 0; i < TM; i++) {
        float vals[TN];
        #pragma unroll
        for (int j = 0; j < TN; j++) {
            float v = acc[i][j] + bv[j];
            if (SILU) {
                v = v / (1.0f + expf(-v));
            }
            vals[j] = v;
        }
        float* out = C + (size_t)(cRowBase + i) * N + cColBase;
        #pragma unroll
        for (int j = 0; j < TN; j += 4) {
            float4 v4 = make_float4(vals[j], vals[j+1], vals[j+2], vals[j+3]);
            *reinterpret_cast<float4*>(out + j) = v4;
        }
    }
}

// ---------------------------------------------------------------------------
// Soft assignment: q[n,c] = (1/(1+d2)) / sum_c (1/(1+d2)); V=1 so exponent = 1.
// One warp per row; lane c (< 20) owns cluster c. Clusters staged in smem.
// ---------------------------------------------------------------------------
__global__ __launch_bounds__(256)
void soft_assign_kernel(const float* __restrict__ Z,       // [N_ROWS, H1]
                        const float* __restrict__ clusters,// [K_CL, H1]
                        float* __restrict__ Q)             // [N_ROWS, K_CL]
{
    __shared__ float sCl[K_CL][H1];   // 20 KB

    const int tid = threadIdx.x;
    for (int i = tid; i < K_CL * H1; i += blockDim.x)
        sCl[i / H1][i % H1] = clusters[i];
    __syncthreads();

    const int warpId = tid >> 5;
    const int lane   = tid & 31;
    const int row    = blockIdx.x * 8 + warpId;
    if (row >= N_ROWS) return;

    const float* z = Z + (size_t)row * H1;

    float d2 = 0.0f;
    if (lane < K_CL) {
        #pragma unroll 8
        for (int d = 0; d < H1; d++) {
            float diff = z[d] - sCl[lane][d];   // z[d] is a warp-uniform load
            d2 = fmaf(diff, diff, d2);
        }
    }
    float q = (lane < K_CL) ? 1.0f / (1.0f + d2) : 0.0f;

    // warp-wide sum
    float s = q;
    #pragma unroll
    for (int off = 16; off > 0; off >>= 1)
        s += __shfl_xor_sync(0xFFFFFFFFu, s, off);

    if (lane < K_CL)
        Q[(size_t)row * K_CL + lane] = q / s;
}

// ---------------------------------------------------------------------------
extern "C" void kernel_launch(void* const* d_in, const int* in_sizes, int n_in,
                              void* d_out, int out_size)
{
    const float* x        = (const float*)d_in[0];   // [N_ROWS, D_IN]
    const float* W1       = (const float*)d_in[1];   // [D_IN, H0]
    const float* b1       = (const float*)d_in[2];   // [H0]
    const float* W2       = (const float*)d_in[3];   // [H0, H1]
    const float* b2       = (const float*)d_in[4];   // [H1]
    const float* clusters = (const float*)d_in[5];   // [K_CL, H1]

    float* z_out = (float*)d_out;                          // [N_ROWS, H1]
    float* q_out = (float*)d_out + (size_t)N_ROWS * H1;    // [N_ROWS, K_CL]

    float* H;
    cudaGetSymbolAddress((void**)&H, g_H);

    // GEMM1: H = silu(x @ W1 + b1)   [32768,3000]x[3000,1024]
    {
        dim3 grid(H0 / BN, N_ROWS / BM);
        sgemm_bias_act<true><<<grid, 256>>>(x, W1, b1, H, N_ROWS, H0, D_IN);
    }
    // GEMM2: Z = H @ W2 + b2   [32768,1024]x[1024,256]
    {
        dim3 grid(H1 / BN, N_ROWS / BM);
        sgemm_bias_act<false><<<grid, 256>>>(H, W2, b2, z_out, N_ROWS, H1, H0);
    }
    // Soft assignment
    {
        dim3 grid(N_ROWS / 8);
        soft_assign_kernel<<<grid, 256>>>(z_out, clusters, q_out);
    }
}

// round 5
// speedup vs baseline: 2.4840x; 2.4825x over previous
#include <cuda_runtime.h>
#include <cuda_bf16.h>
#include <math.h>
#include <stdint.h>

#define N_ROWS 32768
#define D_IN   3000
#define KPAD1  3072
#define H0     1024
#define H1     256
#define K_CL   20

// ---------------- scratch (static device arrays; no allocs) ----------------
__device__ __align__(16) __nv_bfloat16 g_xh[(size_t)N_ROWS * KPAD1];
__device__ __align__(16) __nv_bfloat16 g_xl[(size_t)N_ROWS * KPAD1];
__device__ __align__(16) __nv_bfloat16 g_w1th[(size_t)H0 * KPAD1];
__device__ __align__(16) __nv_bfloat16 g_w1tl[(size_t)H0 * KPAD1];
__device__ __align__(16) __nv_bfloat16 g_hh[(size_t)N_ROWS * H0];
__device__ __align__(16) __nv_bfloat16 g_hl[(size_t)N_ROWS * H0];
__device__ __align__(16) __nv_bfloat16 g_w2th[(size_t)H1 * H0];
__device__ __align__(16) __nv_bfloat16 g_w2tl[(size_t)H1 * H0];

// ---------------- helpers ----------------
__device__ __forceinline__ uint32_t smem_u32(const void* p) {
    uint32_t a;
    asm("{ .reg .u64 t; cvta.to.shared.u64 t, %1; cvt.u32.u64 %0, t; }" : "=r"(a) : "l"(p));
    return a;
}
__device__ __forceinline__ void cp_async16(uint32_t s, const void* g) {
    asm volatile("cp.async.cg.shared.global [%0], [%1], 16;" :: "r"(s), "l"(g));
}
__device__ __forceinline__ void cp_commit() {
    asm volatile("cp.async.commit_group;" ::: "memory");
}
template <int N>
__device__ __forceinline__ void cp_wait() {
    asm volatile("cp.async.wait_group %0;" :: "n"(N) : "memory");
}
__device__ __forceinline__ void ldm_x4(uint32_t* r, uint32_t addr) {
    asm volatile("ldmatrix.sync.aligned.m8n8.x4.shared.b16 {%0,%1,%2,%3}, [%4];"
        : "=r"(r[0]), "=r"(r[1]), "=r"(r[2]), "=r"(r[3]) : "r"(addr));
}
__device__ __forceinline__ void mma_bf16(float* c, const uint32_t* a, const uint32_t* b) {
    asm volatile(
        "mma.sync.aligned.m16n8k16.row.col.f32.bf16.bf16.f32 "
        "{%0,%1,%2,%3}, {%4,%5,%6,%7}, {%8,%9}, {%0,%1,%2,%3};"
        : "+f"(c[0]), "+f"(c[1]), "+f"(c[2]), "+f"(c[3])
        : "r"(a[0]), "r"(a[1]), "r"(a[2]), "r"(a[3]), "r"(b[0]), "r"(b[1]));
}

// ---------------- preprocess kernels ----------------
__global__ __launch_bounds__(256)
void convert_x_kernel(const float* __restrict__ x,
                      __nv_bfloat16* __restrict__ xh,
                      __nv_bfloat16* __restrict__ xl)
{
    const int row = blockIdx.x;
    const float* xr = x + (size_t)row * D_IN;
    __nv_bfloat16* oh = xh + (size_t)row * KPAD1;
    __nv_bfloat16* ol = xl + (size_t)row * KPAD1;
    for (int p = threadIdx.x; p < KPAD1 / 2; p += 256) {
        int c = p * 2;
        float v0 = 0.f, v1 = 0.f;
        if (c < D_IN) {
            float2 v = *reinterpret_cast<const float2*>(xr + c);
            v0 = v.x; v1 = v.y;
        }
        __nv_bfloat16 h0 = __float2bfloat16_rn(v0);
        __nv_bfloat16 h1 = __float2bfloat16_rn(v1);
        __nv_bfloat16 l0 = __float2bfloat16_rn(v0 - __bfloat162float(h0));
        __nv_bfloat16 l1 = __float2bfloat16_rn(v1 - __bfloat162float(h1));
        *reinterpret_cast<__nv_bfloat162*>(oh + c) = __nv_bfloat162(h0, h1);
        *reinterpret_cast<__nv_bfloat162*>(ol + c) = __nv_bfloat162(l0, l1);
    }
}

// W [K, N] fp32 -> Wt hi/lo [N, Kpad] bf16 (transposed, zero-padded K)
__global__ __launch_bounds__(256)
void transpose_split_kernel(const float* __restrict__ W,
                            __nv_bfloat16* __restrict__ Th,
                            __nv_bfloat16* __restrict__ Tl,
                            int K, int N, int Kpad)
{
    __shared__ float s[32][33];
    const int k0 = blockIdx.x * 32;
    const int n0 = blockIdx.y * 32;
    const int tx = threadIdx.x, ty = threadIdx.y;
    #pragma unroll
    for (int j = 0; j < 32; j += 8) {
        int k = k0 + ty + j;
        s[ty + j][tx] = (k < K) ? W[(size_t)k * N + n0 + tx] : 0.0f;
    }
    __syncthreads();
    #pragma unroll
    for (int j = 0; j < 32; j += 8) {
        int n = n0 + ty + j;
        int kk = k0 + tx;
        float v = s[tx][ty + j];
        __nv_bfloat16 hi = __float2bfloat16_rn(v);
        __nv_bfloat16 lo = __float2bfloat16_rn(v - __bfloat162float(hi));
        Th[(size_t)n * Kpad + kk] = hi;
        Tl[(size_t)n * Kpad + kk] = lo;
    }
}

// ---------------- HMMA 3-pass GEMM (mma.sync bf16) ----------------
// CTA tile 128x128, K-chunk 64 bf16 (128B rows, XOR swizzle).
// SMEM stage: [Ah 16K][Al 16K][Bh 16K][Bl 16K] = 64KB; double buffered.
#define TILE_B   16384
#define STAGE_B  (4 * TILE_B)
#define GEMM_SMEM (2 * STAGE_B)   // 131072

__device__ __forceinline__ void load_stage(
    uint32_t sbase, int stage,
    const __nv_bfloat16* __restrict__ Ah, const __nv_bfloat16* __restrict__ Al,
    const __nv_bfloat16* __restrict__ Bh, const __nv_bfloat16* __restrict__ Bl,
    int mBase, int nBase, int Kpad, int kc, int tid)
{
    const uint32_t st = sbase + stage * STAGE_B;
    #pragma unroll
    for (int t = 0; t < 4; t++) {
        const __nv_bfloat16* src = (t == 0) ? Ah : (t == 1) ? Al : (t == 2) ? Bh : Bl;
        const int rbase = (t < 2) ? mBase : nBase;
        #pragma unroll
        for (int it = 0; it < 4; it++) {
            int idx = tid + it * 256;        // 0..1023
            int row = idx >> 3;              // 0..127
            int c   = idx & 7;               // 16B chunk in row
            const char* g = (const char*)(src + (size_t)(rbase + row) * Kpad + kc * 64) + c * 16;
            uint32_t sw = (uint32_t)(row * 128 + ((c * 16) ^ ((row & 7) << 4)));
            cp_async16(st + t * TILE_B + sw, g);
        }
    }
}

// EPI=0: bias+SiLU -> bf16 hi/lo.  EPI=1: bias -> fp32.
template <int EPI>
__global__ __launch_bounds__(256, 1)
void gemm_mma_kernel(const __nv_bfloat16* __restrict__ Ah, const __nv_bfloat16* __restrict__ Al,
                     const __nv_bfloat16* __restrict__ Bh, const __nv_bfloat16* __restrict__ Bl,
                     const float* __restrict__ bias,
                     __nv_bfloat16* __restrict__ OutH, __nv_bfloat16* __restrict__ OutL,
                     float* __restrict__ OutF,
                     int Kpad, int NC, int ldOut)
{
    extern __shared__ char smem[];
    const uint32_t sbase = smem_u32(smem);
    const int tid  = threadIdx.x;
    const int wid  = tid >> 5;
    const int lane = tid & 31;
    const int mBase = blockIdx.y * 128;
    const int nBase = blockIdx.x * 128;
    const int warpM = (wid >> 2) * 64;   // 0 / 64
    const int warpN = (wid & 3) * 32;    // 0..96

    float acc[4][4][4];
    #pragma unroll
    for (int i = 0; i < 4; i++)
        #pragma unroll
        for (int j = 0; j < 4; j++)
            #pragma unroll
            for (int k = 0; k < 4; k++)
                acc[i][j][k] = 0.0f;

    load_stage(sbase, 0, Ah, Al, Bh, Bl, mBase, nBase, Kpad, 0, tid);
    cp_commit();

    // ldmatrix per-lane row offsets (fixed across chunks)
    const int aRowIn = lane & 15;                 // row within 16-row tile
    const int kHalf  = (lane >> 4) << 4;          // 0 / 16 bytes (k 0-7 / 8-15)

    for (int c = 0; c < NC; c++) {
        if (c + 1 < NC) {
            load_stage(sbase, (c + 1) & 1, Ah, Al, Bh, Bl, mBase, nBase, Kpad, c + 1, tid);
            cp_commit();
            cp_wait<1>();
        } else {
            cp_wait<0>();
        }
        __syncthreads();

        const uint32_t st = sbase + (c & 1) * STAGE_B;
        const uint32_t aH = st;
        const uint32_t aL = st + TILE_B;
        const uint32_t bH = st + 2 * TILE_B;
        const uint32_t bL = st + 3 * TILE_B;

        #pragma unroll
        for (int ks = 0; ks < 4; ks++) {
            const int kb = ks * 32 + kHalf;       // byte offset of this k16 half
            uint32_t fah[4][4], fal[4][4], fbh[4][2], fbl[4][2];

            #pragma unroll
            for (int mt = 0; mt < 4; mt++) {
                int row = warpM + mt * 16 + aRowIn;
                uint32_t off = (uint32_t)(row * 128 + (kb ^ ((row & 7) << 4)));
                ldm_x4(fah[mt], aH + off);
                ldm_x4(fal[mt], aL + off);
            }
            #pragma unroll
            for (int nt2 = 0; nt2 < 2; nt2++) {
                int row = warpN + nt2 * 16 + aRowIn;
                uint32_t off = (uint32_t)(row * 128 + (kb ^ ((row & 7) << 4)));
                uint32_t r[4];
                ldm_x4(r, bH + off);
                fbh[nt2 * 2][0] = r[0]; fbh[nt2 * 2][1] = r[2];
                fbh[nt2 * 2 + 1][0] = r[1]; fbh[nt2 * 2 + 1][1] = r[3];
                ldm_x4(r, bL + off);
                fbl[nt2 * 2][0] = r[0]; fbl[nt2 * 2][1] = r[2];
                fbl[nt2 * 2 + 1][0] = r[1]; fbl[nt2 * 2 + 1][1] = r[3];
            }
            #pragma unroll
            for (int mt = 0; mt < 4; mt++)
                #pragma unroll
                for (int nt = 0; nt < 4; nt++) {
                    mma_bf16(acc[mt][nt], fah[mt], fbh[nt]);
                    mma_bf16(acc[mt][nt], fal[mt], fbh[nt]);
                    mma_bf16(acc[mt][nt], fah[mt], fbl[nt]);
                }
        }
        __syncthreads();
    }

    // ---- epilogue ----
    const int rBase = mBase + warpM + (lane >> 2);
    const int cBase = nBase + warpN + (lane & 3) * 2;

    #pragma unroll
    for (int mt = 0; mt < 4; mt++) {
        #pragma unroll
        for (int nt = 0; nt < 4; nt++) {
            const int col = cBase + nt * 8;
            const float b0 = bias[col];
            const float b1 = bias[col + 1];
            #pragma unroll
            for (int h = 0; h < 2; h++) {
                const int row = rBase + mt * 16 + h * 8;
                float v0 = acc[mt][nt][2 * h]     + b0;
                float v1 = acc[mt][nt][2 * h + 1] + b1;
                if (EPI == 0) {
                    v0 = v0 / (1.0f + expf(-v0));
                    v1 = v1 / (1.0f + expf(-v1));
                    __nv_bfloat16 h0 = __float2bfloat16_rn(v0);
                    __nv_bfloat16 h1 = __float2bfloat16_rn(v1);
                    __nv_bfloat16 l0 = __float2bfloat16_rn(v0 - __bfloat162float(h0));
                    __nv_bfloat16 l1 = __float2bfloat16_rn(v1 - __bfloat162float(h1));
                    *reinterpret_cast<__nv_bfloat162*>(OutH + (size_t)row * ldOut + col) = __nv_bfloat162(h0, h1);
                    *reinterpret_cast<__nv_bfloat162*>(OutL + (size_t)row * ldOut + col) = __nv_bfloat162(l0, l1);
                } else {
                    *reinterpret_cast<float2*>(OutF + (size_t)row * ldOut + col) = make_float2(v0, v1);
                }
            }
        }
    }
}

// ---------------- soft assignment (V=1 -> q = 1/(1+d2), row-normalized) ----
__global__ __launch_bounds__(256)
void soft_assign_kernel(const float* __restrict__ Z,
                        const float* __restrict__ clusters,
                        float* __restrict__ Q)
{
    __shared__ float sCl[K_CL][H1];
    const int tid = threadIdx.x;
    for (int i = tid; i < K_CL * H1; i += blockDim.x)
        sCl[i / H1][i % H1] = clusters[i];
    __syncthreads();

    const int warpId = tid >> 5;
    const int lane = tid & 31;
    const int row = blockIdx.x * 8 + warpId;
    if (row >= N_ROWS) return;

    const float* z = Z + (size_t)row * H1;
    float d2 = 0.0f;
    if (lane < K_CL) {
        #pragma unroll 8
        for (int d = 0; d < H1; d++) {
            float diff = z[d] - sCl[lane][d];
            d2 = fmaf(diff, diff, d2);
        }
    }
    float q = (lane < K_CL) ? 1.0f / (1.0f + d2) : 0.0f;
    float s = q;
    #pragma unroll
    for (int off = 16; off > 0; off >>= 1)
        s += __shfl_xor_sync(0xFFFFFFFFu, s, off);
    if (lane < K_CL)
        Q[(size_t)row * K_CL + lane] = q / s;
}

// ---------------- launch ----------------
extern "C" void kernel_launch(void* const* d_in, const int* in_sizes, int n_in,
                              void* d_out, int out_size)
{
    const float* x        = (const float*)d_in[0];
    const float* W1       = (const float*)d_in[1];
    const float* b1       = (const float*)d_in[2];
    const float* W2       = (const float*)d_in[3];
    const float* b2       = (const float*)d_in[4];
    const float* clusters = (const float*)d_in[5];

    float* z_out = (float*)d_out;
    float* q_out = (float*)d_out + (size_t)N_ROWS * H1;

    __nv_bfloat16 *xh, *xl, *w1th, *w1tl, *hh, *hl, *w2th, *w2tl;
    cudaGetSymbolAddress((void**)&xh,   g_xh);
    cudaGetSymbolAddress((void**)&xl,   g_xl);
    cudaGetSymbolAddress((void**)&w1th, g_w1th);
    cudaGetSymbolAddress((void**)&w1tl, g_w1tl);
    cudaGetSymbolAddress((void**)&hh,   g_hh);
    cudaGetSymbolAddress((void**)&hl,   g_hl);
    cudaGetSymbolAddress((void**)&w2th, g_w2th);
    cudaGetSymbolAddress((void**)&w2tl, g_w2tl);

    cudaFuncSetAttribute(gemm_mma_kernel<0>, cudaFuncAttributeMaxDynamicSharedMemorySize, GEMM_SMEM);
    cudaFuncSetAttribute(gemm_mma_kernel<1>, cudaFuncAttributeMaxDynamicSharedMemorySize, GEMM_SMEM);

    // 1) split/convert inputs
    convert_x_kernel<<<N_ROWS, 256>>>(x, xh, xl);
    transpose_split_kernel<<<dim3(KPAD1 / 32, H0 / 32), dim3(32, 8)>>>(W1, w1th, w1tl, D_IN, H0, KPAD1);
    transpose_split_kernel<<<dim3(H0 / 32, H1 / 32), dim3(32, 8)>>>(W2, w2th, w2tl, H0, H1, H0);

    // 2) GEMM1: H = silu(x @ W1 + b1) -> bf16 hi/lo
    gemm_mma_kernel<0><<<dim3(H0 / 128, N_ROWS / 128), 256, GEMM_SMEM>>>(
        xh, xl, w1th, w1tl, b1, hh, hl, nullptr, KPAD1, KPAD1 / 64, H0);

    // 3) GEMM2: z = H @ W2 + b2 -> fp32
    gemm_mma_kernel<1><<<dim3(H1 / 128, N_ROWS / 128), 256, GEMM_SMEM>>>(
        hh, hl, w2th, w2tl, b2, nullptr, nullptr, z_out, H0, H0 / 64, H1);

    // 4) soft assignment
    soft_assign_kernel<<<N_ROWS / 8, 256>>>(z_out, clusters, q_out);
}

// round 6
// speedup vs baseline: 3.3629x; 1.3538x over previous
#include <cuda_runtime.h>
#include <cuda_fp16.h>
#include <math.h>
#include <stdint.h>

#define N_ROWS 32768
#define D_IN   3000
#define KPAD1  3072
#define H0     1024
#define H1     256
#define K_CL   20

// ---------------- scratch (static device arrays; no allocs) ----------------
__device__ __align__(16) __half g_xh[(size_t)N_ROWS * KPAD1];
__device__ __align__(16) __half g_xl[(size_t)N_ROWS * KPAD1];
__device__ __align__(16) __half g_w1t[(size_t)H0 * KPAD1];
__device__ __align__(16) __half g_hh[(size_t)N_ROWS * H0];
__device__ __align__(16) __half g_hl[(size_t)N_ROWS * H0];
__device__ __align__(16) __half g_w2t[(size_t)H1 * H0];

// ---------------- helpers ----------------
__device__ __forceinline__ uint32_t smem_u32(const void* p) {
    uint32_t a;
    asm("{ .reg .u64 t; cvta.to.shared.u64 t, %1; cvt.u32.u64 %0, t; }" : "=r"(a) : "l"(p));
    return a;
}
__device__ __forceinline__ void cp_async16(uint32_t s, const void* g) {
    asm volatile("cp.async.cg.shared.global [%0], [%1], 16;" :: "r"(s), "l"(g));
}
__device__ __forceinline__ void cp_commit() {
    asm volatile("cp.async.commit_group;" ::: "memory");
}
template <int N>
__device__ __forceinline__ void cp_wait() {
    asm volatile("cp.async.wait_group %0;" :: "n"(N) : "memory");
}
__device__ __forceinline__ void ldm_x4(uint32_t* r, uint32_t addr) {
    asm volatile("ldmatrix.sync.aligned.m8n8.x4.shared.b16 {%0,%1,%2,%3}, [%4];"
        : "=r"(r[0]), "=r"(r[1]), "=r"(r[2]), "=r"(r[3]) : "r"(addr));
}
__device__ __forceinline__ void mma_f16(float* c, const uint32_t* a, const uint32_t* b) {
    asm volatile(
        "mma.sync.aligned.m16n8k16.row.col.f32.f16.f16.f32 "
        "{%0,%1,%2,%3}, {%4,%5,%6,%7}, {%8,%9}, {%0,%1,%2,%3};"
        : "+f"(c[0]), "+f"(c[1]), "+f"(c[2]), "+f"(c[3])
        : "r"(a[0]), "r"(a[1]), "r"(a[2]), "r"(a[3]), "r"(b[0]), "r"(b[1]));
}

// ---------------- preprocess kernels ----------------
__global__ __launch_bounds__(256)
void convert_x_kernel(const float* __restrict__ x,
                      __half* __restrict__ xh,
                      __half* __restrict__ xl)
{
    const int row = blockIdx.x;
    const float* xr = x + (size_t)row * D_IN;
    __half* oh = xh + (size_t)row * KPAD1;
    __half* ol = xl + (size_t)row * KPAD1;
    for (int p = threadIdx.x; p < KPAD1 / 2; p += 256) {
        int c = p * 2;
        float v0 = 0.f, v1 = 0.f;
        if (c < D_IN) {
            float2 v = *reinterpret_cast<const float2*>(xr + c);
            v0 = v.x; v1 = v.y;
        }
        __half h0 = __float2half_rn(v0);
        __half h1 = __float2half_rn(v1);
        __half l0 = __float2half_rn(v0 - __half2float(h0));
        __half l1 = __float2half_rn(v1 - __half2float(h1));
        *reinterpret_cast<__half2*>(oh + c) = __halves2half2(h0, h1);
        *reinterpret_cast<__half2*>(ol + c) = __halves2half2(l0, l1);
    }
}

// W [K, N] fp32 -> Wt [N, Kpad] fp16 (transposed, zero-padded K)
__global__ __launch_bounds__(256)
void transpose_kernel(const float* __restrict__ W,
                      __half* __restrict__ T,
                      int K, int N, int Kpad)
{
    __shared__ float s[32][33];
    const int k0 = blockIdx.x * 32;
    const int n0 = blockIdx.y * 32;
    const int tx = threadIdx.x, ty = threadIdx.y;
    #pragma unroll
    for (int j = 0; j < 32; j += 8) {
        int k = k0 + ty + j;
        s[ty + j][tx] = (k < K) ? W[(size_t)k * N + n0 + tx] : 0.0f;
    }
    __syncthreads();
    #pragma unroll
    for (int j = 0; j < 32; j += 8) {
        int n = n0 + ty + j;
        int kk = k0 + tx;
        T[(size_t)n * Kpad + kk] = __float2half_rn(s[tx][ty + j]);
    }
}

// ---------------- HMMA 2-pass fp16 GEMM ----------------
// CTA tile 128x128, K-chunk 64 fp16 (128B rows, XOR swizzle).
// Stage: [Ah 16K][Al 16K][Bh 16K] = 48KB; 3-stage pipeline = 144KB.
#define TILE_B   16384
#define STAGE_B  (3 * TILE_B)
#define NSTAGE   3
#define GEMM_SMEM (NSTAGE * STAGE_B)   // 147456

// EPI=0: bias+SiLU -> fp16 hi/lo.  EPI=1: bias -> fp32.
template <int EPI>
__global__ __launch_bounds__(256, 1)
void gemm_mma_kernel(const __half* __restrict__ Ah, const __half* __restrict__ Al,
                     const __half* __restrict__ Bh,
                     const float* __restrict__ bias,
                     __half* __restrict__ OutH, __half* __restrict__ OutL,
                     float* __restrict__ OutF,
                     int Kpad, int NC, int ldOut)
{
    extern __shared__ char smem[];
    const uint32_t sbase = smem_u32(smem);
    const int tid  = threadIdx.x;
    const int wid  = tid >> 5;
    const int lane = tid & 31;
    const int mBase = blockIdx.y * 128;
    const int nBase = blockIdx.x * 128;
    const int warpM = (wid >> 2) * 64;   // 0 / 64
    const int warpN = (wid & 3) * 32;    // 0..96

    // ---- per-thread load geometry (constant across chunks) ----
    const int row_ld = tid >> 3;          // 0..31
    const int c16    = tid & 7;           // 16B column
    const uint32_t swB = (uint32_t)(row_ld * 128 + ((c16 * 16) ^ ((row_ld & 7) << 4)));
    const char* gA_h = (const char*)(Ah + (size_t)(mBase + row_ld) * Kpad) + c16 * 16;
    const char* gA_l = (const char*)(Al + (size_t)(mBase + row_ld) * Kpad) + c16 * 16;
    const char* gB_h = (const char*)(Bh + (size_t)(nBase + row_ld) * Kpad) + c16 * 16;
    const size_t itStride = (size_t)32 * Kpad * sizeof(__half);   // 32 rows down

    // ---- per-warp ldmatrix offsets, fully precomputed ----
    const int aRowIn = lane & 15;
    const int kHalf  = (lane >> 4) << 4;  // 0 / 16 bytes
    uint32_t offA[4][4], offB[2][4];
    #pragma unroll
    for (int mt = 0; mt < 4; mt++) {
        int row = warpM + mt * 16 + aRowIn;
        int xr = (row & 7) << 4;
        #pragma unroll
        for (int ks = 0; ks < 4; ks++)
            offA[mt][ks] = (uint32_t)(row * 128 + ((ks * 32 + kHalf) ^ xr));
    }
    #pragma unroll
    for (int nt2 = 0; nt2 < 2; nt2++) {
        int row = warpN + nt2 * 16 + aRowIn;
        int xr = (row & 7) << 4;
        #pragma unroll
        for (int ks = 0; ks < 4; ks++)
            offB[nt2][ks] = (uint32_t)(row * 128 + ((ks * 32 + kHalf) ^ xr));
    }

    float acc[4][4][4];
    #pragma unroll
    for (int i = 0; i < 4; i++)
        #pragma unroll
        for (int j = 0; j < 4; j++)
            #pragma unroll
            for (int k = 0; k < 4; k++)
                acc[i][j][k] = 0.0f;

    // ---- pipelined loads ----
    auto load_stage = [&](int stage) {
        const uint32_t st = sbase + stage * STAGE_B;
        #pragma unroll
        for (int it = 0; it < 4; it++) {
            cp_async16(st + 0 * TILE_B + swB + it * 4096, gA_h + it * itStride);
            cp_async16(st + 1 * TILE_B + swB + it * 4096, gA_l + it * itStride);
            cp_async16(st + 2 * TILE_B + swB + it * 4096, gB_h + it * itStride);
        }
        gA_h += 128; gA_l += 128; gB_h += 128;   // next 64-element K chunk
        cp_commit();
    };

    load_stage(0);
    load_stage(1);

    int sCompute = 0, sLoad = 2;
    for (int c = 0; c < NC; c++) {
        if (c == NC - 1) cp_wait<0>(); else cp_wait<1>();
        __syncthreads();
        if (c + 2 < NC) {
            load_stage(sLoad);
            if (++sLoad == NSTAGE) sLoad = 0;
        }

        const uint32_t st = sbase + sCompute * STAGE_B;
        if (++sCompute == NSTAGE) sCompute = 0;

        #pragma unroll
        for (int ks = 0; ks < 4; ks++) {
            uint32_t fah[4][4], fal[4][4], fbh[4][2];
            #pragma unroll
            for (int mt = 0; mt < 4; mt++) {
                ldm_x4(fah[mt], st + offA[mt][ks]);
                ldm_x4(fal[mt], st + TILE_B + offA[mt][ks]);
            }
            #pragma unroll
            for (int nt2 = 0; nt2 < 2; nt2++) {
                uint32_t r[4];
                ldm_x4(r, st + 2 * TILE_B + offB[nt2][ks]);
                fbh[nt2 * 2][0] = r[0]; fbh[nt2 * 2][1] = r[2];
                fbh[nt2 * 2 + 1][0] = r[1]; fbh[nt2 * 2 + 1][1] = r[3];
            }
            #pragma unroll
            for (int mt = 0; mt < 4; mt++)
                #pragma unroll
                for (int nt = 0; nt < 4; nt++) {
                    mma_f16(acc[mt][nt], fah[mt], fbh[nt]);
                    mma_f16(acc[mt][nt], fal[mt], fbh[nt]);
                }
        }
    }

    // ---- epilogue ----
    const int rBase = mBase + warpM + (lane >> 2);
    const int cBase = nBase + warpN + (lane & 3) * 2;

    #pragma unroll
    for (int mt = 0; mt < 4; mt++) {
        #pragma unroll
        for (int nt = 0; nt < 4; nt++) {
            const int col = cBase + nt * 8;
            const float b0 = bias[col];
            const float b1 = bias[col + 1];
            #pragma unroll
            for (int h = 0; h < 2; h++) {
                const int row = rBase + mt * 16 + h * 8;
                float v0 = acc[mt][nt][2 * h]     + b0;
                float v1 = acc[mt][nt][2 * h + 1] + b1;
                if (EPI == 0) {
                    v0 = v0 / (1.0f + expf(-v0));
                    v1 = v1 / (1.0f + expf(-v1));
                    __half h0 = __float2half_rn(v0);
                    __half h1 = __float2half_rn(v1);
                    __half l0 = __float2half_rn(v0 - __half2float(h0));
                    __half l1 = __float2half_rn(v1 - __half2float(h1));
                    *reinterpret_cast<__half2*>(OutH + (size_t)row * ldOut + col) = __halves2half2(h0, h1);
                    *reinterpret_cast<__half2*>(OutL + (size_t)row * ldOut + col) = __halves2half2(l0, l1);
                } else {
                    *reinterpret_cast<float2*>(OutF + (size_t)row * ldOut + col) = make_float2(v0, v1);
                }
            }
        }
    }
}

// ---------------- soft assignment (V=1 -> q = 1/(1+d2), row-normalized) ----
__global__ __launch_bounds__(256)
void soft_assign_kernel(const float* __restrict__ Z,
                        const float* __restrict__ clusters,
                        float* __restrict__ Q)
{
    __shared__ float sCl[K_CL][H1];
    const int tid = threadIdx.x;
    for (int i = tid; i < K_CL * H1; i += blockDim.x)
        sCl[i / H1][i % H1] = clusters[i];
    __syncthreads();

    const int warpId = tid >> 5;
    const int lane = tid & 31;
    const int row = blockIdx.x * 8 + warpId;
    if (row >= N_ROWS) return;

    const float* z = Z + (size_t)row * H1;
    float d2 = 0.0f;
    if (lane < K_CL) {
        #pragma unroll 8
        for (int d = 0; d < H1; d++) {
            float diff = z[d] - sCl[lane][d];
            d2 = fmaf(diff, diff, d2);
        }
    }
    float q = (lane < K_CL) ? 1.0f / (1.0f + d2) : 0.0f;
    float s = q;
    #pragma unroll
    for (int off = 16; off > 0; off >>= 1)
        s += __shfl_xor_sync(0xFFFFFFFFu, s, off);
    if (lane < K_CL)
        Q[(size_t)row * K_CL + lane] = q / s;
}

// ---------------- launch ----------------
extern "C" void kernel_launch(void* const* d_in, const int* in_sizes, int n_in,
                              void* d_out, int out_size)
{
    const float* x        = (const float*)d_in[0];
    const float* W1       = (const float*)d_in[1];
    const float* b1       = (const float*)d_in[2];
    const float* W2       = (const float*)d_in[3];
    const float* b2       = (const float*)d_in[4];
    const float* clusters = (const float*)d_in[5];

    float* z_out = (float*)d_out;
    float* q_out = (float*)d_out + (size_t)N_ROWS * H1;

    __half *xh, *xl, *w1t, *hh, *hl, *w2t;
    cudaGetSymbolAddress((void**)&xh,  g_xh);
    cudaGetSymbolAddress((void**)&xl,  g_xl);
    cudaGetSymbolAddress((void**)&w1t, g_w1t);
    cudaGetSymbolAddress((void**)&hh,  g_hh);
    cudaGetSymbolAddress((void**)&hl,  g_hl);
    cudaGetSymbolAddress((void**)&w2t, g_w2t);

    cudaFuncSetAttribute(gemm_mma_kernel<0>, cudaFuncAttributeMaxDynamicSharedMemorySize, GEMM_SMEM);
    cudaFuncSetAttribute(gemm_mma_kernel<1>, cudaFuncAttributeMaxDynamicSharedMemorySize, GEMM_SMEM);

    // 1) split/convert inputs
    convert_x_kernel<<<N_ROWS, 256>>>(x, xh, xl);
    transpose_kernel<<<dim3(KPAD1 / 32, H0 / 32), dim3(32, 8)>>>(W1, w1t, D_IN, H0, KPAD1);
    transpose_kernel<<<dim3(H0 / 32, H1 / 32), dim3(32, 8)>>>(W2, w2t, H0, H1, H0);

    // 2) GEMM1: H = silu(x @ W1 + b1) -> fp16 hi/lo (2-pass fp16 MMA)
    gemm_mma_kernel<0><<<dim3(H0 / 128, N_ROWS / 128), 256, GEMM_SMEM>>>(
        xh, xl, w1t, b1, hh, hl, nullptr, KPAD1, KPAD1 / 64, H0);

    // 3) GEMM2: z = H @ W2 + b2 -> fp32
    gemm_mma_kernel<1><<<dim3(H1 / 128, N_ROWS / 128), 256, GEMM_SMEM>>>(
        hh, hl, w2t, b2, nullptr, nullptr, z_out, H0, H0 / 64, H1);

    // 4) soft assignment
    soft_assign_kernel<<<N_ROWS / 8, 256>>>(z_out, clusters, q_out);
}

// round 7
// speedup vs baseline: 6.3552x; 1.8898x over previous
#include <cuda_runtime.h>
#include <cuda_fp16.h>
#include <math.h>
#include <stdint.h>

#define N_ROWS 32768
#define D_IN   3000
#define KPAD1  3072
#define H0     1024
#define H1     256
#define K_CL   20

// ---------------- scratch (static device arrays; no allocs) ----------------
__device__ __align__(16) __half g_xh[(size_t)N_ROWS * KPAD1];
__device__ __align__(16) __half g_w1t[(size_t)H0 * KPAD1];
__device__ __align__(16) __half g_hh[(size_t)N_ROWS * H0];
__device__ __align__(16) __half g_w2t[(size_t)H1 * H0];

// ---------------- helpers ----------------
__device__ __forceinline__ uint32_t smem_u32(const void* p) {
    uint32_t a;
    asm("{ .reg .u64 t; cvta.to.shared.u64 t, %1; cvt.u32.u64 %0, t; }" : "=r"(a) : "l"(p));
    return a;
}
__device__ __forceinline__ void cp_async16(uint32_t s, const void* g) {
    asm volatile("cp.async.cg.shared.global [%0], [%1], 16;" :: "r"(s), "l"(g));
}
__device__ __forceinline__ void cp_commit() {
    asm volatile("cp.async.commit_group;" ::: "memory");
}
template <int N>
__device__ __forceinline__ void cp_wait() {
    asm volatile("cp.async.wait_group %0;" :: "n"(N) : "memory");
}
__device__ __forceinline__ void ldm_x4(uint32_t* r, uint32_t addr) {
    asm volatile("ldmatrix.sync.aligned.m8n8.x4.shared.b16 {%0,%1,%2,%3}, [%4];"
        : "=r"(r[0]), "=r"(r[1]), "=r"(r[2]), "=r"(r[3]) : "r"(addr));
}
__device__ __forceinline__ void mma_f16(float* c, const uint32_t* a, const uint32_t* b) {
    asm volatile(
        "mma.sync.aligned.m16n8k16.row.col.f32.f16.f16.f32 "
        "{%0,%1,%2,%3}, {%4,%5,%6,%7}, {%8,%9}, {%0,%1,%2,%3};"
        : "+f"(c[0]), "+f"(c[1]), "+f"(c[2]), "+f"(c[3])
        : "r"(a[0]), "r"(a[1]), "r"(a[2]), "r"(a[3]), "r"(b[0]), "r"(b[1]));
}

// ---------------- preprocess kernels ----------------
__global__ __launch_bounds__(256)
void convert_x_kernel(const float* __restrict__ x,
                      __half* __restrict__ xh)
{
    const int row = blockIdx.x;
    const float* xr = x + (size_t)row * D_IN;
    __half* oh = xh + (size_t)row * KPAD1;
    for (int p = threadIdx.x; p < KPAD1 / 2; p += 256) {
        int c = p * 2;
        float v0 = 0.f, v1 = 0.f;
        if (c < D_IN) {
            float2 v = *reinterpret_cast<const float2*>(xr + c);
            v0 = v.x; v1 = v.y;
        }
        *reinterpret_cast<__half2*>(oh + c) =
            __halves2half2(__float2half_rn(v0), __float2half_rn(v1));
    }
}

// W [K, N] fp32 -> Wt [N, Kpad] fp16 (transposed, zero-padded K)
__global__ __launch_bounds__(256)
void transpose_kernel(const float* __restrict__ W,
                      __half* __restrict__ T,
                      int K, int N, int Kpad)
{
    __shared__ float s[32][33];
    const int k0 = blockIdx.x * 32;
    const int n0 = blockIdx.y * 32;
    const int tx = threadIdx.x, ty = threadIdx.y;
    #pragma unroll
    for (int j = 0; j < 32; j += 8) {
        int k = k0 + ty + j;
        s[ty + j][tx] = (k < K) ? W[(size_t)k * N + n0 + tx] : 0.0f;
    }
    __syncthreads();
    #pragma unroll
    for (int j = 0; j < 32; j += 8) {
        int n = n0 + ty + j;
        int kk = k0 + tx;
        T[(size_t)n * Kpad + kk] = __float2half_rn(s[tx][ty + j]);
    }
}

// ---------------- HMMA single-pass fp16 GEMM ----------------
// CTA tile 128x256, warp tile 64x64 (8 warps, 2x4), K-chunk 64 fp16.
// Stage: [A 16K][B 32K] = 48KB; 3-stage pipeline = 144KB.
#define TILE_A   16384
#define TILE_B2  32768
#define STAGE_B  (TILE_A + TILE_B2)
#define NSTAGE   3
#define GEMM_SMEM (NSTAGE * STAGE_B)   // 147456

// EPI=0: bias+SiLU -> fp16.  EPI=1: bias -> fp32.
template <int EPI>
__global__ __launch_bounds__(256, 1)
void gemm_mma_kernel(const __half* __restrict__ A,
                     const __half* __restrict__ B,
                     const float* __restrict__ bias,
                     __half* __restrict__ OutH,
                     float* __restrict__ OutF,
                     int Kpad, int NC, int ldOut)
{
    extern __shared__ char smem[];
    const uint32_t sbase = smem_u32(smem);
    const int tid  = threadIdx.x;
    const int wid  = tid >> 5;
    const int lane = tid & 31;
    const int mBase = blockIdx.y * 128;
    const int nBase = blockIdx.x * 256;
    const int warpM = (wid & 1) * 64;    // 0 / 64
    const int warpN = (wid >> 1) * 64;   // 0..192

    // ---- per-thread load geometry (constant across chunks) ----
    const int row_ld = tid >> 3;          // 0..31
    const int c16    = tid & 7;           // 16B column
    const uint32_t swB = (uint32_t)(row_ld * 128 + ((c16 * 16) ^ ((row_ld & 7) << 4)));
    const char* gA = (const char*)(A + (size_t)(mBase + row_ld) * Kpad) + c16 * 16;
    const char* gB = (const char*)(B + (size_t)(nBase + row_ld) * Kpad) + c16 * 16;
    const size_t itStride = (size_t)32 * Kpad * sizeof(__half);   // 32 rows down

    // ---- per-warp ldmatrix offsets, fully precomputed ----
    const int aRowIn = lane & 15;
    const int kHalf  = (lane >> 4) << 4;  // 0 / 16 bytes
    uint32_t offA[4][4], offB[4][4];
    #pragma unroll
    for (int mt = 0; mt < 4; mt++) {
        int row = warpM + mt * 16 + aRowIn;
        int xr = (row & 7) << 4;
        #pragma unroll
        for (int ks = 0; ks < 4; ks++)
            offA[mt][ks] = (uint32_t)(row * 128 + ((ks * 32 + kHalf) ^ xr));
    }
    #pragma unroll
    for (int nt2 = 0; nt2 < 4; nt2++) {
        int row = warpN + nt2 * 16 + aRowIn;
        int xr = (row & 7) << 4;
        #pragma unroll
        for (int ks = 0; ks < 4; ks++)
            offB[nt2][ks] = (uint32_t)(row * 128 + ((ks * 32 + kHalf) ^ xr));
    }

    float acc[4][8][4];
    #pragma unroll
    for (int i = 0; i < 4; i++)
        #pragma unroll
        for (int j = 0; j < 8; j++)
            #pragma unroll
            for (int k = 0; k < 4; k++)
                acc[i][j][k] = 0.0f;

    // ---- pipelined loads ----
    auto load_stage = [&](int stage) {
        const uint32_t st = sbase + stage * STAGE_B;
        #pragma unroll
        for (int it = 0; it < 4; it++)
            cp_async16(st + swB + it * 4096, gA + it * itStride);
        #pragma unroll
        for (int it = 0; it < 8; it++)
            cp_async16(st + TILE_A + swB + it * 4096, gB + it * itStride);
        gA += 128; gB += 128;   // next 64-element K chunk
        cp_commit();
    };

    load_stage(0);
    load_stage(1);

    int sCompute = 0, sLoad = 2;
    for (int c = 0; c < NC; c++) {
        if (c == NC - 1) cp_wait<0>(); else cp_wait<1>();
        __syncthreads();
        if (c + 2 < NC) {
            load_stage(sLoad);
            if (++sLoad == NSTAGE) sLoad = 0;
        }

        const uint32_t st = sbase + sCompute * STAGE_B;
        if (++sCompute == NSTAGE) sCompute = 0;

        #pragma unroll
        for (int ks = 0; ks < 4; ks++) {
            uint32_t fa[4][4], fb[8][2];
            #pragma unroll
            for (int mt = 0; mt < 4; mt++)
                ldm_x4(fa[mt], st + offA[mt][ks]);
            #pragma unroll
            for (int nt2 = 0; nt2 < 4; nt2++) {
                uint32_t r[4];
                ldm_x4(r, st + TILE_A + offB[nt2][ks]);
                fb[nt2 * 2][0] = r[0]; fb[nt2 * 2][1] = r[2];
                fb[nt2 * 2 + 1][0] = r[1]; fb[nt2 * 2 + 1][1] = r[3];
            }
            #pragma unroll
            for (int mt = 0; mt < 4; mt++)
                #pragma unroll
                for (int nt = 0; nt < 8; nt++)
                    mma_f16(acc[mt][nt], fa[mt], fb[nt]);
        }
    }

    // ---- epilogue ----
    const int rBase = mBase + warpM + (lane >> 2);
    const int cBase = nBase + warpN + (lane & 3) * 2;

    #pragma unroll
    for (int mt = 0; mt < 4; mt++) {
        #pragma unroll
        for (int nt = 0; nt < 8; nt++) {
            const int col = cBase + nt * 8;
            const float b0 = bias[col];
            const float b1 = bias[col + 1];
            #pragma unroll
            for (int h = 0; h < 2; h++) {
                const int row = rBase + mt * 16 + h * 8;
                float v0 = acc[mt][nt][2 * h]     + b0;
                float v1 = acc[mt][nt][2 * h + 1] + b1;
                if (EPI == 0) {
                    v0 = v0 / (1.0f + expf(-v0));
                    v1 = v1 / (1.0f + expf(-v1));
                    *reinterpret_cast<__half2*>(OutH + (size_t)row * ldOut + col) =
                        __halves2half2(__float2half_rn(v0), __float2half_rn(v1));
                } else {
                    *reinterpret_cast<float2*>(OutF + (size_t)row * ldOut + col) = make_float2(v0, v1);
                }
            }
        }
    }
}

// ---------------- soft assignment (V=1 -> q = 1/(1+d2), row-normalized) ----
__global__ __launch_bounds__(256)
void soft_assign_kernel(const float* __restrict__ Z,
                        const float* __restrict__ clusters,
                        float* __restrict__ Q)
{
    __shared__ float sCl[K_CL][H1 + 1];   // +1 pad: conflict-free lane-strided reads
    const int tid = threadIdx.x;
    for (int i = tid; i < K_CL * H1; i += blockDim.x)
        sCl[i / H1][i % H1] = clusters[i];
    __syncthreads();

    const int warpId = tid >> 5;
    const int lane = tid & 31;
    const int row = blockIdx.x * 8 + warpId;
    if (row >= N_ROWS) return;

    const float* z = Z + (size_t)row * H1;
    float d2 = 0.0f;
    if (lane < K_CL) {
        #pragma unroll 8
        for (int d = 0; d < H1; d++) {
            float diff = z[d] - sCl[lane][d];
            d2 = fmaf(diff, diff, d2);
        }
    }
    float q = (lane < K_CL) ? 1.0f / (1.0f + d2) : 0.0f;
    float s = q;
    #pragma unroll
    for (int off = 16; off > 0; off >>= 1)
        s += __shfl_xor_sync(0xFFFFFFFFu, s, off);
    if (lane < K_CL)
        Q[(size_t)row * K_CL + lane] = q / s;
}

// ---------------- launch ----------------
extern "C" void kernel_launch(void* const* d_in, const int* in_sizes, int n_in,
                              void* d_out, int out_size)
{
    const float* x        = (const float*)d_in[0];
    const float* W1       = (const float*)d_in[1];
    const float* b1       = (const float*)d_in[2];
    const float* W2       = (const float*)d_in[3];
    const float* b2       = (const float*)d_in[4];
    const float* clusters = (const float*)d_in[5];

    float* z_out = (float*)d_out;
    float* q_out = (float*)d_out + (size_t)N_ROWS * H1;

    __half *xh, *w1t, *hh, *w2t;
    cudaGetSymbolAddress((void**)&xh,  g_xh);
    cudaGetSymbolAddress((void**)&w1t, g_w1t);
    cudaGetSymbolAddress((void**)&hh,  g_hh);
    cudaGetSymbolAddress((void**)&w2t, g_w2t);

    cudaFuncSetAttribute(gemm_mma_kernel<0>, cudaFuncAttributeMaxDynamicSharedMemorySize, GEMM_SMEM);
    cudaFuncSetAttribute(gemm_mma_kernel<1>, cudaFuncAttributeMaxDynamicSharedMemorySize, GEMM_SMEM);

    // 1) convert inputs to fp16
    convert_x_kernel<<<N_ROWS, 256>>>(x, xh);
    transpose_kernel<<<dim3(KPAD1 / 32, H0 / 32), dim3(32, 8)>>>(W1, w1t, D_IN, H0, KPAD1);
    transpose_kernel<<<dim3(H0 / 32, H1 / 32), dim3(32, 8)>>>(W2, w2t, H0, H1, H0);

    // 2) GEMM1: H = silu(x @ W1 + b1) -> fp16
    gemm_mma_kernel<0><<<dim3(H0 / 256, N_ROWS / 128), 256, GEMM_SMEM>>>(
        xh, w1t, b1, hh, nullptr, KPAD1, KPAD1 / 64, H0);

    // 3) GEMM2: z = H @ W2 + b2 -> fp32
    gemm_mma_kernel<1><<<dim3(H1 / 256, N_ROWS / 128), 256, GEMM_SMEM>>>(
        hh, w2t, b2, nullptr, z_out, H0, H0 / 64, H1);

    // 4) soft assignment
    soft_assign_kernel<<<N_ROWS / 8, 256>>>(z_out, clusters, q_out);
}

// round 8
// speedup vs baseline: 6.8057x; 1.0709x over previous
#include <cuda_runtime.h>
#include <cuda_fp16.h>
#include <math.h>
#include <stdint.h>

#define N_ROWS 32768
#define D_IN   3000
#define KPAD1  3072
#define H0     1024
#define H1     256
#define K_CL   20

// ---------------- scratch (static device arrays; no allocs) ----------------
__device__ __align__(16) __half g_xh[(size_t)N_ROWS * KPAD1];
__device__ __align__(16) __half g_w1t[(size_t)H0 * KPAD1];
__device__ __align__(16) __half g_hh[(size_t)N_ROWS * H0];
__device__ __align__(16) __half g_w2t[(size_t)H1 * H0];

// ---------------- helpers ----------------
__device__ __forceinline__ uint32_t smem_u32(const void* p) {
    uint32_t a;
    asm("{ .reg .u64 t; cvta.to.shared.u64 t, %1; cvt.u32.u64 %0, t; }" : "=r"(a) : "l"(p));
    return a;
}
__device__ __forceinline__ void cp_async16(uint32_t s, const void* g) {
    asm volatile("cp.async.cg.shared.global [%0], [%1], 16;" :: "r"(s), "l"(g));
}
__device__ __forceinline__ void cp_commit() {
    asm volatile("cp.async.commit_group;" ::: "memory");
}
template <int N>
__device__ __forceinline__ void cp_wait() {
    asm volatile("cp.async.wait_group %0;" :: "n"(N) : "memory");
}
__device__ __forceinline__ void ldm_x4(uint32_t* r, uint32_t addr) {
    asm volatile("ldmatrix.sync.aligned.m8n8.x4.shared.b16 {%0,%1,%2,%3}, [%4];"
        : "=r"(r[0]), "=r"(r[1]), "=r"(r[2]), "=r"(r[3]) : "r"(addr));
}
__device__ __forceinline__ void mma_f16(float* c, const uint32_t* a, const uint32_t* b) {
    asm volatile(
        "mma.sync.aligned.m16n8k16.row.col.f32.f16.f16.f32 "
        "{%0,%1,%2,%3}, {%4,%5,%6,%7}, {%8,%9}, {%0,%1,%2,%3};"
        : "+f"(c[0]), "+f"(c[1]), "+f"(c[2]), "+f"(c[3])
        : "r"(a[0]), "r"(a[1]), "r"(a[2]), "r"(a[3]), "r"(b[0]), "r"(b[1]));
}

// ---------------- preprocess kernels ----------------
__global__ __launch_bounds__(256)
void convert_x_kernel(const float* __restrict__ x,
                      __half* __restrict__ xh)
{
    const int row = blockIdx.x;
    const float* xr = x + (size_t)row * D_IN;
    __half* oh = xh + (size_t)row * KPAD1;
    for (int p = threadIdx.x; p < KPAD1 / 2; p += 256) {
        int c = p * 2;
        float v0 = 0.f, v1 = 0.f;
        if (c < D_IN) {
            float2 v = *reinterpret_cast<const float2*>(xr + c);
            v0 = v.x; v1 = v.y;
        }
        *reinterpret_cast<__half2*>(oh + c) =
            __halves2half2(__float2half_rn(v0), __float2half_rn(v1));
    }
}

// W [K, N] fp32 -> Wt [N, Kpad] fp16 (transposed, zero-padded K)
__global__ __launch_bounds__(256)
void transpose_kernel(const float* __restrict__ W,
                      __half* __restrict__ T,
                      int K, int N, int Kpad)
{
    __shared__ float s[32][33];
    const int k0 = blockIdx.x * 32;
    const int n0 = blockIdx.y * 32;
    const int tx = threadIdx.x, ty = threadIdx.y;
    #pragma unroll
    for (int j = 0; j < 32; j += 8) {
        int k = k0 + ty + j;
        s[ty + j][tx] = (k < K) ? W[(size_t)k * N + n0 + tx] : 0.0f;
    }
    __syncthreads();
    #pragma unroll
    for (int j = 0; j < 32; j += 8) {
        int n = n0 + ty + j;
        int kk = k0 + tx;
        T[(size_t)n * Kpad + kk] = __float2half_rn(s[tx][ty + j]);
    }
}

// ---------------- HMMA single-pass fp16 GEMM ----------------
// CTA tile 128x128, warp tile 64x32 (8 warps, 2x4), K-chunk 64 fp16.
// Stage: [A 16K][B 16K] = 32KB; 3-stage pipeline = 96KB -> 2 CTAs/SM.
#define TILE_A   16384
#define STAGE_B  32768
#define NSTAGE   3
#define GEMM_SMEM (NSTAGE * STAGE_B)   // 98304

// EPI=0: bias+SiLU -> fp16.  EPI=1: bias -> fp32.
template <int EPI>
__global__ __launch_bounds__(256, 2)
void gemm_mma_kernel(const __half* __restrict__ A,
                     const __half* __restrict__ B,
                     const float* __restrict__ bias,
                     __half* __restrict__ OutH,
                     float* __restrict__ OutF,
                     int Kpad, int NC, int ldOut)
{
    extern __shared__ char smem[];
    const uint32_t sbase = smem_u32(smem);
    const int tid  = threadIdx.x;
    const int wid  = tid >> 5;
    const int lane = tid & 31;
    const int mBase = blockIdx.y * 128;
    const int nBase = blockIdx.x * 128;
    const int warpM = (wid & 1) * 64;    // 0 / 64
    const int warpN = (wid >> 1) * 32;   // 0..96

    // ---- per-thread load geometry (constant across chunks) ----
    const int row_ld = tid >> 3;          // 0..31
    const int c16    = tid & 7;           // 16B column
    const uint32_t swB = (uint32_t)(row_ld * 128 + ((c16 * 16) ^ ((row_ld & 7) << 4)));
    const char* gA = (const char*)(A + (size_t)(mBase + row_ld) * Kpad) + c16 * 16;
    const char* gB = (const char*)(B + (size_t)(nBase + row_ld) * Kpad) + c16 * 16;
    const size_t itStride = (size_t)32 * Kpad * sizeof(__half);   // 32 rows down

    // ---- per-warp ldmatrix offsets, fully precomputed ----
    const int aRowIn = lane & 15;
    const int kHalf  = (lane >> 4) << 4;  // 0 / 16 bytes
    uint32_t offA[4][4], offB[2][4];
    #pragma unroll
    for (int mt = 0; mt < 4; mt++) {
        int row = warpM + mt * 16 + aRowIn;
        int xr = (row & 7) << 4;
        #pragma unroll
        for (int ks = 0; ks < 4; ks++)
            offA[mt][ks] = (uint32_t)(row * 128 + ((ks * 32 + kHalf) ^ xr));
    }
    #pragma unroll
    for (int nt2 = 0; nt2 < 2; nt2++) {
        int row = warpN + nt2 * 16 + aRowIn;
        int xr = (row & 7) << 4;
        #pragma unroll
        for (int ks = 0; ks < 4; ks++)
            offB[nt2][ks] = (uint32_t)(row * 128 + ((ks * 32 + kHalf) ^ xr));
    }

    float acc[4][4][4];
    #pragma unroll
    for (int i = 0; i < 4; i++)
        #pragma unroll
        for (int j = 0; j < 4; j++)
            #pragma unroll
            for (int k = 0; k < 4; k++)
                acc[i][j][k] = 0.0f;

    // ---- pipelined loads ----
    auto load_stage = [&](int stage) {
        const uint32_t st = sbase + stage * STAGE_B;
        #pragma unroll
        for (int it = 0; it < 4; it++)
            cp_async16(st + swB + it * 4096, gA + it * itStride);
        #pragma unroll
        for (int it = 0; it < 4; it++)
            cp_async16(st + TILE_A + swB + it * 4096, gB + it * itStride);
        gA += 128; gB += 128;   // next 64-element K chunk
        cp_commit();
    };

    load_stage(0);
    load_stage(1);

    int sCompute = 0, sLoad = 2;
    for (int c = 0; c < NC; c++) {
        if (c == NC - 1) cp_wait<0>(); else cp_wait<1>();
        __syncthreads();
        if (c + 2 < NC) {
            load_stage(sLoad);
            if (++sLoad == NSTAGE) sLoad = 0;
        }

        const uint32_t st = sbase + sCompute * STAGE_B;
        if (++sCompute == NSTAGE) sCompute = 0;

        #pragma unroll
        for (int ks = 0; ks < 4; ks++) {
            uint32_t fa[4][4], fb[4][2];
            #pragma unroll
            for (int mt = 0; mt < 4; mt++)
                ldm_x4(fa[mt], st + offA[mt][ks]);
            #pragma unroll
            for (int nt2 = 0; nt2 < 2; nt2++) {
                uint32_t r[4];
                ldm_x4(r, st + TILE_A + offB[nt2][ks]);
                fb[nt2 * 2][0] = r[0]; fb[nt2 * 2][1] = r[2];
                fb[nt2 * 2 + 1][0] = r[1]; fb[nt2 * 2 + 1][1] = r[3];
            }
            #pragma unroll
            for (int mt = 0; mt < 4; mt++)
                #pragma unroll
                for (int nt = 0; nt < 4; nt++)
                    mma_f16(acc[mt][nt], fa[mt], fb[nt]);
        }
    }

    // ---- epilogue ----
    const int rBase = mBase + warpM + (lane >> 2);
    const int cBase = nBase + warpN + (lane & 3) * 2;

    #pragma unroll
    for (int mt = 0; mt < 4; mt++) {
        #pragma unroll
        for (int nt = 0; nt < 4; nt++) {
            const int col = cBase + nt * 8;
            const float b0 = bias[col];
            const float b1 = bias[col + 1];
            #pragma unroll
            for (int h = 0; h < 2; h++) {
                const int row = rBase + mt * 16 + h * 8;
                float v0 = acc[mt][nt][2 * h]     + b0;
                float v1 = acc[mt][nt][2 * h + 1] + b1;
                if (EPI == 0) {
                    v0 = v0 / (1.0f + expf(-v0));
                    v1 = v1 / (1.0f + expf(-v1));
                    *reinterpret_cast<__half2*>(OutH + (size_t)row * ldOut + col) =
                        __halves2half2(__float2half_rn(v0), __float2half_rn(v1));
                } else {
                    *reinterpret_cast<float2*>(OutF + (size_t)row * ldOut + col) = make_float2(v0, v1);
                }
            }
        }
    }
}

// ---------------- soft assignment (V=1 -> q = 1/(1+d2), row-normalized) ----
__global__ __launch_bounds__(256)
void soft_assign_kernel(const float* __restrict__ Z,
                        const float* __restrict__ clusters,
                        float* __restrict__ Q)
{
    __shared__ float sCl[K_CL][H1 + 1];   // +1 pad: conflict-free lane-strided reads
    const int tid = threadIdx.x;
    for (int i = tid; i < K_CL * H1; i += blockDim.x)
        sCl[i / H1][i % H1] = clusters[i];
    __syncthreads();

    const int warpId = tid >> 5;
    const int lane = tid & 31;
    const int row = blockIdx.x * 8 + warpId;
    if (row >= N_ROWS) return;

    const float* z = Z + (size_t)row * H1;
    float d2 = 0.0f;
    if (lane < K_CL) {
        #pragma unroll 8
        for (int d = 0; d < H1; d++) {
            float diff = z[d] - sCl[lane][d];
            d2 = fmaf(diff, diff, d2);
        }
    }
    float q = (lane < K_CL) ? 1.0f / (1.0f + d2) : 0.0f;
    float s = q;
    #pragma unroll
    for (int off = 16; off > 0; off >>= 1)
        s += __shfl_xor_sync(0xFFFFFFFFu, s, off);
    if (lane < K_CL)
        Q[(size_t)row * K_CL + lane] = q / s;
}

// ---------------- launch ----------------
extern "C" void kernel_launch(void* const* d_in, const int* in_sizes, int n_in,
                              void* d_out, int out_size)
{
    const float* x        = (const float*)d_in[0];
    const float* W1       = (const float*)d_in[1];
    const float* b1       = (const float*)d_in[2];
    const float* W2       = (const float*)d_in[3];
    const float* b2       = (const float*)d_in[4];
    const float* clusters = (const float*)d_in[5];

    float* z_out = (float*)d_out;
    float* q_out = (float*)d_out + (size_t)N_ROWS * H1;

    __half *xh, *w1t, *hh, *w2t;
    cudaGetSymbolAddress((void**)&xh,  g_xh);
    cudaGetSymbolAddress((void**)&w1t, g_w1t);
    cudaGetSymbolAddress((void**)&hh,  g_hh);
    cudaGetSymbolAddress((void**)&w2t, g_w2t);

    cudaFuncSetAttribute(gemm_mma_kernel<0>, cudaFuncAttributeMaxDynamicSharedMemorySize, GEMM_SMEM);
    cudaFuncSetAttribute(gemm_mma_kernel<1>, cudaFuncAttributeMaxDynamicSharedMemorySize, GEMM_SMEM);

    // 1) convert inputs to fp16
    convert_x_kernel<<<N_ROWS, 256>>>(x, xh);
    transpose_kernel<<<dim3(KPAD1 / 32, H0 / 32), dim3(32, 8)>>>(W1, w1t, D_IN, H0, KPAD1);
    transpose_kernel<<<dim3(H0 / 32, H1 / 32), dim3(32, 8)>>>(W2, w2t, H0, H1, H0);

    // 2) GEMM1: H = silu(x @ W1 + b1) -> fp16
    gemm_mma_kernel<0><<<dim3(H0 / 128, N_ROWS / 128), 256, GEMM_SMEM>>>(
        xh, w1t, b1, hh, nullptr, KPAD1, KPAD1 / 64, H0);

    // 3) GEMM2: z = H @ W2 + b2 -> fp32
    gemm_mma_kernel<1><<<dim3(H1 / 128, N_ROWS / 128), 256, GEMM_SMEM>>>(
        hh, w2t, b2, nullptr, z_out, H0, H0 / 64, H1);

    // 4) soft assignment
    soft_assign_kernel<<<N_ROWS / 8, 256>>>(z_out, clusters, q_out);
}